// round 7
// baseline (speedup 1.0000x reference)
#include <cuda_runtime.h>
#include <math.h>

#define S_LEN 512
#define BATCH 64
#define DIN   256
#define H     512
#define G3H   1536          // 3*H
#define SCALE 1.25f         // 1/(1-0.2)
#define NBLK  128           // persistent grid size (<= 148 SMs -> all co-resident)

// ---------------- scratch (device globals; no cudaMalloc allowed) ----------------
__device__ float g_gi[(size_t)S_LEN * BATCH * G3H];   // 192 MiB, reused both layers
__device__ float g_out0[(size_t)S_LEN * BATCH * H];   // 64 MiB, layer-0 outputs
__device__ float g_h[2][BATCH * H];                   // double-buffered hidden state
__device__ unsigned g_bar;                            // grid barrier counter
__device__ unsigned char g_mask[4][BATCH * H];        // canonical uint8 masks
__device__ int g_mcode;                               // 0=int32, 1=uint8, 2=float32, 3=bf16

// ---- detect mask transport dtype from bit patterns of mask_in0 ----
// mask_in0 has 16384 elements; scan first 4096 32-bit words (safe: >=16384 bytes
// in every candidate dtype). Bool 0/1 data signatures:
//   int32  : words are 0x00000000 / 0x00000001
//   uint8  : bytes 0/1 packed -> upper bytes of words often nonzero, never 0x3F80 halfwords
//   float32: words 0x00000000 / 0x3F800000
//   bf16   : halfwords 0x0000 / 0x3F80 -> LOW halfword 0x3F80 occurs (~20% of words),
//            which never happens for f32 (low halfword of 1.0f is 0x0000).
__global__ void detect_mask_dtype_kernel(const unsigned* __restrict__ m) {
    __shared__ int saw_bf16lo, saw_f32, saw_upper;
    if (threadIdx.x == 0) { saw_bf16lo = 0; saw_f32 = 0; saw_upper = 0; }
    __syncthreads();
    for (int i = threadIdx.x; i < 4096; i += blockDim.x) {
        unsigned w = m[i];
        if ((w & 0xFFFFu) == 0x3F80u) atomicOr(&saw_bf16lo, 1);
        if (w == 0x3F800000u)         atomicOr(&saw_f32, 1);
        else if (w != 0u && (w & 0xFFFFFF00u) != 0u && (w & 0xFFFFu) != 0x3F80u)
            atomicOr(&saw_upper, 1);
    }
    __syncthreads();
    if (threadIdx.x == 0)
        g_mcode = saw_bf16lo ? 3 : (saw_f32 ? 2 : (saw_upper ? 1 : 0));
}

// normalize one mask into canonical uint8 (nonzero -> 1)
__global__ void convert_mask_kernel(const void* __restrict__ src,
                                    unsigned char* __restrict__ dst, int n) {
    int i = blockIdx.x * blockDim.x + threadIdx.x;
    if (i < n) {
        int c = g_mcode;
        unsigned char v;
        if (c == 0)      v = ((const int*)src)[i] != 0;
        else if (c == 1) v = ((const unsigned char*)src)[i] != 0;
        else if (c == 2) v = ((const float*)src)[i] != 0.f;
        else             v = ((const unsigned short*)src)[i] != 0;
        dst[i] = v;
    }
}

// reset barrier counter + zero h0
__global__ void reset_kernel(float* h0, int n) {
    int i = blockIdx.x * blockDim.x + threadIdx.x;
    if (i == 0) g_bar = 0u;
    if (i < n) h0[i] = 0.f;
}

__global__ void copy_kernel(const float* __restrict__ src, float* __restrict__ dst, int n) {
    int i = blockIdx.x * blockDim.x + threadIdx.x;
    if (i < n) dst[i] = src[i];
}

// ---- C[M][1536] = drop(A)[M][K] @ W[1536][K]^T + bias ----
// A is [S*B, K]; dropout mask is [B, K] canonical uint8, row b = m % BATCH.
// classic 128x128x8 tile, 256 threads, 8x8 microtile
__global__ void __launch_bounds__(256) sgemm_mask_bias_kernel(
    const float* __restrict__ A, const unsigned char* __restrict__ mask,
    const float* __restrict__ W, const float* __restrict__ bias,
    float* __restrict__ C, int K)
{
    __shared__ float As[8][128];
    __shared__ float Bs[8][128];

    int tid = threadIdx.x;
    int tx = tid % 16;            // n-microtile
    int ty = tid / 16;            // m-microtile
    int row0 = blockIdx.y * 128;  // m
    int col0 = blockIdx.x * 128;  // n

    int la_r = tid >> 1;          // 0..127
    int la_c = (tid & 1) * 4;     // 0 or 4

    int arow = row0 + la_r;
    int b    = arow % BATCH;
    const float* Aptr = A + (size_t)arow * K + la_c;
    const unsigned char* Mptr = mask + (size_t)b * K + la_c;
    const float* Wptr = W + (size_t)(col0 + la_r) * K + la_c;

    float acc[8][8];
    #pragma unroll
    for (int i = 0; i < 8; i++)
        #pragma unroll
        for (int j = 0; j < 8; j++) acc[i][j] = 0.f;

    for (int k0 = 0; k0 < K; k0 += 8) {
        float4 a4 = *(const float4*)(Aptr + k0);
        uchar4 m4 = *(const uchar4*)(Mptr + k0);
        float4 b4 = *(const float4*)(Wptr + k0);
        As[la_c + 0][la_r] = m4.x ? 0.f : a4.x * SCALE;
        As[la_c + 1][la_r] = m4.y ? 0.f : a4.y * SCALE;
        As[la_c + 2][la_r] = m4.z ? 0.f : a4.z * SCALE;
        As[la_c + 3][la_r] = m4.w ? 0.f : a4.w * SCALE;
        Bs[la_c + 0][la_r] = b4.x; Bs[la_c + 1][la_r] = b4.y;
        Bs[la_c + 2][la_r] = b4.z; Bs[la_c + 3][la_r] = b4.w;
        __syncthreads();
        #pragma unroll
        for (int k = 0; k < 8; k++) {
            float af[8], bf[8];
            #pragma unroll
            for (int i = 0; i < 8; i++) af[i] = As[k][ty * 8 + i];
            #pragma unroll
            for (int j = 0; j < 8; j++) bf[j] = Bs[k][tx * 8 + j];
            #pragma unroll
            for (int i = 0; i < 8; i++)
                #pragma unroll
                for (int j = 0; j < 8; j++) acc[i][j] += af[i] * bf[j];
        }
        __syncthreads();
    }

    #pragma unroll
    for (int i = 0; i < 8; i++) {
        int m = row0 + ty * 8 + i;
        #pragma unroll
        for (int j = 0; j < 8; j += 4) {
            int n = col0 + tx * 8 + j;
            float4 v;
            v.x = acc[i][j + 0] + bias[n + 0];
            v.y = acc[i][j + 1] + bias[n + 1];
            v.z = acc[i][j + 2] + bias[n + 2];
            v.w = acc[i][j + 3] + bias[n + 3];
            *(float4*)&C[(size_t)m * G3H + n] = v;
        }
    }
}

// ---------------- persistent GRU layer: all 512 steps in one launch ----------------
// grid: NBLK=128 blocks: jt = bid & 15 (32 j's), bt = bid >> 4 (8 batches)
// block: 256 threads (8 warps). warp = K-split slice (64 k), lane = j in tile.
// Grid barrier between steps (monotonic counter; reset_kernel zeroes it first).
__global__ void __launch_bounds__(256) gru_layer_kernel(
    float* __restrict__ h0buf, float* __restrict__ h1buf,
    const float* __restrict__ gi,            // [S][B][3H]
    const float* __restrict__ w_hh,          // [1536][512]
    const float* __restrict__ b_hh,          // [1536]
    const unsigned char* __restrict__ mask_h,// [B][H] canonical uint8
    float* __restrict__ out)                 // [S][B][H]
{
    __shared__ float hd_s[8 * H];                 // dropped hidden, 8 batches (16 KB)
    __shared__ float red_s[8][3][8][32];          // ksplit x gate x b x j (24 KB)

    int tid  = threadIdx.x;
    int lane = tid & 31;
    int warp = tid >> 5;
    int jbase = (blockIdx.x & 15) * 32;
    int bbase = (blockIdx.x >> 4) * 8;

    int j  = jbase + lane;
    int k0 = warp * 64;
    const float4* wr = (const float4*)(w_hh + ((size_t)(0 * H + j)) * H + k0);
    const float4* wz = (const float4*)(w_hh + ((size_t)(1 * H + j)) * H + k0);
    const float4* wn = (const float4*)(w_hh + ((size_t)(2 * H + j)) * H + k0);

    float brc = b_hh[j];
    float bzc = b_hh[H + j];
    float bnc = b_hh[2 * H + j];

    const uchar4* mrow4 = (const uchar4*)(mask_h + (size_t)bbase * H);

    unsigned target = gridDim.x;

    for (int s = 0; s < S_LEN; s++) {
        const float* h_in  = (s & 1) ? h1buf : h0buf;
        float*       h_out = (s & 1) ? h0buf : h1buf;
        const float* gi_s  = gi  + (size_t)s * BATCH * G3H;
        float*       out_s = out + (size_t)s * BATCH * H;

        // load + drop hidden rows for this block's 8 batches (h via L2: .cg)
        const float4* hrow4 = (const float4*)(h_in + (size_t)bbase * H);
        for (int i = tid; i < 8 * H / 4; i += 256) {
            float4 h4 = __ldcg(hrow4 + i);
            uchar4 m4 = mrow4[i];
            hd_s[i * 4 + 0] = m4.x ? 0.f : h4.x * SCALE;
            hd_s[i * 4 + 1] = m4.y ? 0.f : h4.y * SCALE;
            hd_s[i * 4 + 2] = m4.z ? 0.f : h4.z * SCALE;
            hd_s[i * 4 + 3] = m4.w ? 0.f : h4.w * SCALE;
        }
        __syncthreads();

        float ar[8], az[8], an[8];
        #pragma unroll
        for (int i = 0; i < 8; i++) { ar[i] = 0.f; az[i] = 0.f; an[i] = 0.f; }

        #pragma unroll
        for (int q = 0; q < 16; q++) {
            float4 r4 = wr[q];
            float4 z4 = wz[q];
            float4 n4 = wn[q];
            #pragma unroll
            for (int i = 0; i < 8; i++) {
                float4 h4 = *(const float4*)&hd_s[i * H + k0 + q * 4];
                ar[i] += h4.x * r4.x + h4.y * r4.y + h4.z * r4.z + h4.w * r4.w;
                az[i] += h4.x * z4.x + h4.y * z4.y + h4.z * z4.z + h4.w * z4.w;
                an[i] += h4.x * n4.x + h4.y * n4.y + h4.z * n4.z + h4.w * n4.w;
            }
        }

        #pragma unroll
        for (int i = 0; i < 8; i++) {
            red_s[warp][0][i][lane] = ar[i];
            red_s[warp][1][i][lane] = az[i];
            red_s[warp][2][i][lane] = an[i];
        }
        __syncthreads();

        // epilogue: warp i owns local batch i (8 warps x 32 lanes = 8b x 32j)
        {
            int i = warp;
            int b = bbase + i;
            float sr = 0.f, sz = 0.f, sn = 0.f;
            #pragma unroll
            for (int w = 0; w < 8; w++) {
                sr += red_s[w][0][i][lane];
                sz += red_s[w][1][i][lane];
                sn += red_s[w][2][i][lane];
            }
            const float* gib = gi_s + (size_t)b * G3H;
            float gr = __ldcg(gib + j);
            float gz = __ldcg(gib + H + j);
            float gn = __ldcg(gib + 2 * H + j);
            float r = 1.f / (1.f + expf(-(gr + sr + brc)));
            float z = 1.f / (1.f + expf(-(gz + sz + bzc)));
            float n = tanhf(gn + r * (sn + bnc));
            float hd = hd_s[i * H + j];
            float hnew = (1.f - z) * n + z * hd;
            h_out[(size_t)b * H + j] = hnew;
            out_s[(size_t)b * H + j] = hnew;
        }

        // ---- grid barrier: release (fence) -> arrive -> spin -> block sync ----
        __threadfence();
        __syncthreads();
        if (tid == 0) {
            atomicAdd(&g_bar, 1u);
            while (*(volatile unsigned*)&g_bar < target) { }
        }
        __syncthreads();
        target += gridDim.x;
    }
}

// ---------------- launch ----------------
extern "C" void kernel_launch(void* const* d_in, const int* in_sizes, int n_in,
                              void* d_out, int out_size) {
    const float* x     = (const float*)d_in[0];
    const void*  min0  = d_in[1];
    const void*  mh0   = d_in[2];
    const void*  min1  = d_in[3];
    const void*  mh1   = d_in[4];
    const float* w_ih0 = (const float*)d_in[5];
    const float* w_hh0 = (const float*)d_in[6];
    const float* b_ih0 = (const float*)d_in[7];
    const float* b_hh0 = (const float*)d_in[8];
    const float* w_ih1 = (const float*)d_in[9];
    const float* w_hh1 = (const float*)d_in[10];
    const float* b_ih1 = (const float*)d_in[11];
    const float* b_hh1 = (const float*)d_in[12];
    float* out = (float*)d_out;

    float *gi, *out0, *hbuf;
    unsigned char* mbuf;
    cudaGetSymbolAddress((void**)&gi,   g_gi);
    cudaGetSymbolAddress((void**)&out0, g_out0);
    cudaGetSymbolAddress((void**)&hbuf, g_h);
    cudaGetSymbolAddress((void**)&mbuf, g_mask);
    float* h0 = hbuf;
    float* h1 = hbuf + BATCH * H;
    unsigned char* cmin0 = mbuf + 0 * BATCH * H;
    unsigned char* cmh0  = mbuf + 1 * BATCH * H;
    unsigned char* cmin1 = mbuf + 2 * BATCH * H;
    unsigned char* cmh1  = mbuf + 3 * BATCH * H;

    const int M = S_LEN * BATCH;                 // 32768
    dim3 gemm_grid(G3H / 128, M / 128);          // (12, 256)
    const int BH = BATCH * H;                    // 32768

    // ---- normalize masks to uint8 regardless of transport dtype ----
    detect_mask_dtype_kernel<<<1, 256>>>((const unsigned*)min0);
    convert_mask_kernel<<<(BATCH * DIN + 255) / 256, 256>>>(min0, cmin0, BATCH * DIN);
    convert_mask_kernel<<<(BH + 255) / 256, 256>>>(mh0,  cmh0,  BH);
    convert_mask_kernel<<<(BH + 255) / 256, 256>>>(min1, cmin1, BH);
    convert_mask_kernel<<<(BH + 255) / 256, 256>>>(mh1,  cmh1,  BH);

    // ===== layer 0 =====
    sgemm_mask_bias_kernel<<<gemm_grid, 256>>>(x, cmin0, w_ih0, b_ih0, gi, DIN);
    reset_kernel<<<(BH + 255) / 256, 256>>>(h0, BH);
    gru_layer_kernel<<<NBLK, 256>>>(h0, h1, gi, w_hh0, b_hh0, cmh0, out0);

    // ===== layer 1 =====
    sgemm_mask_bias_kernel<<<gemm_grid, 256>>>(out0, cmin1, w_ih1, b_ih1, gi, H);
    reset_kernel<<<(BH + 255) / 256, 256>>>(h0, BH);
    gru_layer_kernel<<<NBLK, 256>>>(h0, h1, gi, w_hh1, b_hh1, cmh1, out);

    // h_last == out1[S-1]
    copy_kernel<<<(BH + 255) / 256, 256>>>(out + (size_t)(S_LEN - 1) * BH,
                                           out + (size_t)S_LEN * BH, BH);
}

// round 8
// speedup vs baseline: 1.0206x; 1.0206x over previous
#include <cuda_runtime.h>
#include <math.h>

#define S_LEN 512
#define BATCH 64
#define DIN   256
#define H     512
#define G3H   1536          // 3*H
#define SCALE 1.25f         // 1/(1-0.2)
#define NBLK  128           // persistent grid size (<= 148 SMs -> all co-resident)

// ---------------- packed f32x2 helpers (FFMA2: 2x fp32 per issue, IEEE-exact) ----
struct alignas(16) ULL2 { unsigned long long x, y; };

__device__ __forceinline__ void ffma2(unsigned long long& d,
                                      unsigned long long a, unsigned long long b) {
    asm("fma.rn.f32x2 %0, %1, %2, %0;" : "+l"(d) : "l"(a), "l"(b));
}
__device__ __forceinline__ unsigned long long pack_dup(float a) {
    unsigned long long d; unsigned r = __float_as_uint(a);
    asm("mov.b64 %0, {%1, %1};" : "=l"(d) : "r"(r));
    return d;
}
__device__ __forceinline__ void unpack2(unsigned long long v, float& lo, float& hi) {
    unsigned l, h;
    asm("mov.b64 {%0, %1}, %2;" : "=r"(l), "=r"(h) : "l"(v));
    lo = __uint_as_float(l); hi = __uint_as_float(h);
}
__device__ __forceinline__ float sum2(unsigned long long v) {
    float lo, hi; unpack2(v, lo, hi); return lo + hi;
}

// ---------------- scratch (device globals; no cudaMalloc allowed) ----------------
__device__ float g_gi[(size_t)S_LEN * BATCH * G3H];   // 192 MiB, reused both layers
__device__ float g_out0[(size_t)S_LEN * BATCH * H];   // 64 MiB, layer-0 outputs
__device__ float g_h[2][BATCH * H];                   // double-buffered hidden state
__device__ unsigned g_bar[8];                         // per-batch-group barrier counters
__device__ unsigned char g_mask[4][BATCH * H];        // canonical uint8 masks
__device__ int g_mcode;                               // 0=int32, 1=uint8, 2=float32, 3=bf16

// ---- detect mask transport dtype from bit patterns of mask_in0 ----
__global__ void detect_mask_dtype_kernel(const unsigned* __restrict__ m) {
    __shared__ int saw_bf16lo, saw_f32, saw_upper;
    if (threadIdx.x == 0) { saw_bf16lo = 0; saw_f32 = 0; saw_upper = 0; }
    __syncthreads();
    for (int i = threadIdx.x; i < 4096; i += blockDim.x) {
        unsigned w = m[i];
        if ((w & 0xFFFFu) == 0x3F80u) atomicOr(&saw_bf16lo, 1);
        if (w == 0x3F800000u)         atomicOr(&saw_f32, 1);
        else if (w != 0u && (w & 0xFFFFFF00u) != 0u && (w & 0xFFFFu) != 0x3F80u)
            atomicOr(&saw_upper, 1);
    }
    __syncthreads();
    if (threadIdx.x == 0)
        g_mcode = saw_bf16lo ? 3 : (saw_f32 ? 2 : (saw_upper ? 1 : 0));
}

// normalize one mask into canonical uint8 (nonzero -> 1)
__global__ void convert_mask_kernel(const void* __restrict__ src,
                                    unsigned char* __restrict__ dst, int n) {
    int i = blockIdx.x * blockDim.x + threadIdx.x;
    if (i < n) {
        int c = g_mcode;
        unsigned char v;
        if (c == 0)      v = ((const int*)src)[i] != 0;
        else if (c == 1) v = ((const unsigned char*)src)[i] != 0;
        else if (c == 2) v = ((const float*)src)[i] != 0.f;
        else             v = ((const unsigned short*)src)[i] != 0;
        dst[i] = v;
    }
}

// reset barrier counters + zero h0
__global__ void reset_kernel(float* h0, int n) {
    int i = blockIdx.x * blockDim.x + threadIdx.x;
    if (i < 8) g_bar[i] = 0u;
    if (i < n) h0[i] = 0.f;
}

__global__ void copy_kernel(const float* __restrict__ src, float* __restrict__ dst, int n) {
    int i = blockIdx.x * blockDim.x + threadIdx.x;
    if (i < n) dst[i] = src[i];
}

// ---- C[M][1536] = drop(A)[M][K] @ W[1536][K]^T + bias ----
// 128x128x8 tile, 256 threads, 8x8 microtile, f32x2-packed accumulation.
__global__ void __launch_bounds__(256) sgemm_mask_bias_kernel(
    const float* __restrict__ A, const unsigned char* __restrict__ mask,
    const float* __restrict__ W, const float* __restrict__ bias,
    float* __restrict__ C, int K)
{
    __shared__ float As[8][128];
    __shared__ float Bs[8][128];

    int tid = threadIdx.x;
    int tx = tid % 16;            // n-microtile
    int ty = tid / 16;            // m-microtile
    int row0 = blockIdx.y * 128;  // m
    int col0 = blockIdx.x * 128;  // n

    int la_r = tid >> 1;          // 0..127
    int la_c = (tid & 1) * 4;     // 0 or 4

    int arow = row0 + la_r;
    int b    = arow % BATCH;
    const float* Aptr = A + (size_t)arow * K + la_c;
    const unsigned char* Mptr = mask + (size_t)b * K + la_c;
    const float* Wptr = W + (size_t)(col0 + la_r) * K + la_c;

    unsigned long long acc2[8][4];   // 8 rows x 4 f32x2 pairs (= 8 cols)
    #pragma unroll
    for (int i = 0; i < 8; i++)
        #pragma unroll
        for (int j = 0; j < 4; j++) acc2[i][j] = 0ull;

    for (int k0 = 0; k0 < K; k0 += 8) {
        float4 a4 = *(const float4*)(Aptr + k0);
        uchar4 m4 = *(const uchar4*)(Mptr + k0);
        float4 b4 = *(const float4*)(Wptr + k0);
        As[la_c + 0][la_r] = m4.x ? 0.f : a4.x * SCALE;
        As[la_c + 1][la_r] = m4.y ? 0.f : a4.y * SCALE;
        As[la_c + 2][la_r] = m4.z ? 0.f : a4.z * SCALE;
        As[la_c + 3][la_r] = m4.w ? 0.f : a4.w * SCALE;
        Bs[la_c + 0][la_r] = b4.x; Bs[la_c + 1][la_r] = b4.y;
        Bs[la_c + 2][la_r] = b4.z; Bs[la_c + 3][la_r] = b4.w;
        __syncthreads();
        #pragma unroll
        for (int k = 0; k < 8; k++) {
            float4 af0 = *(const float4*)&As[k][ty * 8];
            float4 af1 = *(const float4*)&As[k][ty * 8 + 4];
            ULL2 bb0 = *(const ULL2*)&Bs[k][tx * 8];       // 2 packed pairs
            ULL2 bb1 = *(const ULL2*)&Bs[k][tx * 8 + 4];   // 2 packed pairs
            float af[8] = {af0.x, af0.y, af0.z, af0.w, af1.x, af1.y, af1.z, af1.w};
            #pragma unroll
            for (int i = 0; i < 8; i++) {
                unsigned long long a2 = pack_dup(af[i]);
                ffma2(acc2[i][0], a2, bb0.x);
                ffma2(acc2[i][1], a2, bb0.y);
                ffma2(acc2[i][2], a2, bb1.x);
                ffma2(acc2[i][3], a2, bb1.y);
            }
        }
        __syncthreads();
    }

    #pragma unroll
    for (int i = 0; i < 8; i++) {
        int m = row0 + ty * 8 + i;
        int n = col0 + tx * 8;
        float4 v0, v1;
        unpack2(acc2[i][0], v0.x, v0.y);
        unpack2(acc2[i][1], v0.z, v0.w);
        unpack2(acc2[i][2], v1.x, v1.y);
        unpack2(acc2[i][3], v1.z, v1.w);
        v0.x += bias[n + 0]; v0.y += bias[n + 1];
        v0.z += bias[n + 2]; v0.w += bias[n + 3];
        v1.x += bias[n + 4]; v1.y += bias[n + 5];
        v1.z += bias[n + 6]; v1.w += bias[n + 7];
        *(float4*)&C[(size_t)m * G3H + n]     = v0;
        *(float4*)&C[(size_t)m * G3H + n + 4] = v1;
    }
}

// ---------------- persistent GRU layer: all 512 steps in one launch ----------------
// grid: NBLK=128 blocks: jt = bid & 15 (32 j's), bt = bid >> 4 (8 batches).
// Blocks only exchange h within their batch-group (same bt) -> 8 independent
// 16-CTA barriers. warp = K-split slice (64 k), lane = j in tile. f32x2 dots.
__global__ void __launch_bounds__(256) gru_layer_kernel(
    float* __restrict__ h0buf, float* __restrict__ h1buf,
    const float* __restrict__ gi,            // [S][B][3H]
    const float* __restrict__ w_hh,          // [1536][512]
    const float* __restrict__ b_hh,          // [1536]
    const unsigned char* __restrict__ mask_h,// [B][H] canonical uint8
    float* __restrict__ out)                 // [S][B][H]
{
    __shared__ float hd_s[8 * H];                 // dropped hidden, 8 batches (16 KB)
    __shared__ float red_s[8][3][8][32];          // ksplit x gate x b x j (24 KB)

    int tid  = threadIdx.x;
    int lane = tid & 31;
    int warp = tid >> 5;
    int jbase = (blockIdx.x & 15) * 32;
    int grp   = blockIdx.x >> 4;                  // batch group 0..7
    int bbase = grp * 8;

    int j  = jbase + lane;
    int k0 = warp * 64;
    const ULL2* wr2 = (const ULL2*)(w_hh + ((size_t)(0 * H + j)) * H + k0);
    const ULL2* wz2 = (const ULL2*)(w_hh + ((size_t)(1 * H + j)) * H + k0);
    const ULL2* wn2 = (const ULL2*)(w_hh + ((size_t)(2 * H + j)) * H + k0);

    float brc = b_hh[j];
    float bzc = b_hh[H + j];
    float bnc = b_hh[2 * H + j];

    const uchar4* mrow4 = (const uchar4*)(mask_h + (size_t)bbase * H);

    unsigned target = 16u;

    for (int s = 0; s < S_LEN; s++) {
        const float* h_in  = (s & 1) ? h1buf : h0buf;
        float*       h_out = (s & 1) ? h0buf : h1buf;
        const float* gi_s  = gi  + (size_t)s * BATCH * G3H;
        float*       out_s = out + (size_t)s * BATCH * H;

        // load + drop hidden rows for this group's 8 batches (h via L2: .cg)
        const float4* hrow4 = (const float4*)(h_in + (size_t)bbase * H);
        for (int i = tid; i < 8 * H / 4; i += 256) {
            float4 h4 = __ldcg(hrow4 + i);
            uchar4 m4 = mrow4[i];
            hd_s[i * 4 + 0] = m4.x ? 0.f : h4.x * SCALE;
            hd_s[i * 4 + 1] = m4.y ? 0.f : h4.y * SCALE;
            hd_s[i * 4 + 2] = m4.z ? 0.f : h4.z * SCALE;
            hd_s[i * 4 + 3] = m4.w ? 0.f : h4.w * SCALE;
        }
        __syncthreads();

        unsigned long long ar2[8], az2[8], an2[8];
        #pragma unroll
        for (int i = 0; i < 8; i++) { ar2[i] = 0ull; az2[i] = 0ull; an2[i] = 0ull; }

        #pragma unroll
        for (int q = 0; q < 16; q++) {
            ULL2 r2 = wr2[q];
            ULL2 z2 = wz2[q];
            ULL2 n2 = wn2[q];
            #pragma unroll
            for (int i = 0; i < 8; i++) {
                ULL2 h2 = *(const ULL2*)&hd_s[i * H + k0 + q * 4];
                ffma2(ar2[i], h2.x, r2.x); ffma2(ar2[i], h2.y, r2.y);
                ffma2(az2[i], h2.x, z2.x); ffma2(az2[i], h2.y, z2.y);
                ffma2(an2[i], h2.x, n2.x); ffma2(an2[i], h2.y, n2.y);
            }
        }

        #pragma unroll
        for (int i = 0; i < 8; i++) {
            red_s[warp][0][i][lane] = sum2(ar2[i]);
            red_s[warp][1][i][lane] = sum2(az2[i]);
            red_s[warp][2][i][lane] = sum2(an2[i]);
        }
        __syncthreads();

        // epilogue: warp i owns local batch i (8 warps x 32 lanes = 8b x 32j)
        {
            int i = warp;
            int b = bbase + i;
            float sr = 0.f, sz = 0.f, sn = 0.f;
            #pragma unroll
            for (int w = 0; w < 8; w++) {
                sr += red_s[w][0][i][lane];
                sz += red_s[w][1][i][lane];
                sn += red_s[w][2][i][lane];
            }
            const float* gib = gi_s + (size_t)b * G3H;
            float gr = __ldcg(gib + j);
            float gz = __ldcg(gib + H + j);
            float gn = __ldcg(gib + 2 * H + j);
            float r = 1.f / (1.f + expf(-(gr + sr + brc)));
            float z = 1.f / (1.f + expf(-(gz + sz + bzc)));
            float n = tanhf(gn + r * (sn + bnc));
            float hd = hd_s[i * H + j];
            float hnew = (1.f - z) * n + z * hd;
            __stcg(&h_out[(size_t)b * H + j], hnew);
            __stcg(&out_s[(size_t)b * H + j], hnew);
        }

        // ---- group barrier (16 CTAs sharing this batch group) ----
        __threadfence();
        __syncthreads();
        if (tid == 0) {
            atomicAdd(&g_bar[grp], 1u);
            while (*(volatile unsigned*)&g_bar[grp] < target) { }
        }
        __syncthreads();
        target += 16u;
    }
}

// ---------------- launch ----------------
extern "C" void kernel_launch(void* const* d_in, const int* in_sizes, int n_in,
                              void* d_out, int out_size) {
    const float* x     = (const float*)d_in[0];
    const void*  min0  = d_in[1];
    const void*  mh0   = d_in[2];
    const void*  min1  = d_in[3];
    const void*  mh1   = d_in[4];
    const float* w_ih0 = (const float*)d_in[5];
    const float* w_hh0 = (const float*)d_in[6];
    const float* b_ih0 = (const float*)d_in[7];
    const float* b_hh0 = (const float*)d_in[8];
    const float* w_ih1 = (const float*)d_in[9];
    const float* w_hh1 = (const float*)d_in[10];
    const float* b_ih1 = (const float*)d_in[11];
    const float* b_hh1 = (const float*)d_in[12];
    float* out = (float*)d_out;

    float *gi, *out0, *hbuf;
    unsigned char* mbuf;
    cudaGetSymbolAddress((void**)&gi,   g_gi);
    cudaGetSymbolAddress((void**)&out0, g_out0);
    cudaGetSymbolAddress((void**)&hbuf, g_h);
    cudaGetSymbolAddress((void**)&mbuf, g_mask);
    float* h0 = hbuf;
    float* h1 = hbuf + BATCH * H;
    unsigned char* cmin0 = mbuf + 0 * BATCH * H;
    unsigned char* cmh0  = mbuf + 1 * BATCH * H;
    unsigned char* cmin1 = mbuf + 2 * BATCH * H;
    unsigned char* cmh1  = mbuf + 3 * BATCH * H;

    const int M = S_LEN * BATCH;                 // 32768
    dim3 gemm_grid(G3H / 128, M / 128);          // (12, 256)
    const int BH = BATCH * H;                    // 32768

    // ---- normalize masks to uint8 regardless of transport dtype ----
    detect_mask_dtype_kernel<<<1, 256>>>((const unsigned*)min0);
    convert_mask_kernel<<<(BATCH * DIN + 255) / 256, 256>>>(min0, cmin0, BATCH * DIN);
    convert_mask_kernel<<<(BH + 255) / 256, 256>>>(mh0,  cmh0,  BH);
    convert_mask_kernel<<<(BH + 255) / 256, 256>>>(min1, cmin1, BH);
    convert_mask_kernel<<<(BH + 255) / 256, 256>>>(mh1,  cmh1,  BH);

    // ===== layer 0 =====
    sgemm_mask_bias_kernel<<<gemm_grid, 256>>>(x, cmin0, w_ih0, b_ih0, gi, DIN);
    reset_kernel<<<(BH + 255) / 256, 256>>>(h0, BH);
    gru_layer_kernel<<<NBLK, 256>>>(h0, h1, gi, w_hh0, b_hh0, cmh0, out0);

    // ===== layer 1 =====
    sgemm_mask_bias_kernel<<<gemm_grid, 256>>>(out0, cmin1, w_ih1, b_ih1, gi, H);
    reset_kernel<<<(BH + 255) / 256, 256>>>(h0, BH);
    gru_layer_kernel<<<NBLK, 256>>>(h0, h1, gi, w_hh1, b_hh1, cmh1, out);

    // h_last == out1[S-1]
    copy_kernel<<<(BH + 255) / 256, 256>>>(out + (size_t)(S_LEN - 1) * BH,
                                           out + (size_t)S_LEN * BH, BH);
}

// round 10
// speedup vs baseline: 1.1769x; 1.1531x over previous
#include <cuda_runtime.h>
#include <math.h>

#define S_LEN 512
#define BATCH 64
#define DIN   256
#define H     512
#define G3H   1536          // 3*H
#define SCALE 1.25f         // 1/(1-0.2)
#define NBLK  128           // persistent grid size (<= 148 SMs -> all co-resident)

#define GRU_SMEM_BYTES (16 * H * 4 + 8 * 16 * 3 * 17 * 4)   // 32768 + 26112 = 58880

// ---------------- packed f32x2 helpers (FFMA2: 2x fp32 per issue, IEEE-exact) ----
struct alignas(16) ULL2 { unsigned long long x, y; };

__device__ __forceinline__ void ffma2(unsigned long long& d,
                                      unsigned long long a, unsigned long long b) {
    asm("fma.rn.f32x2 %0, %1, %2, %0;" : "+l"(d) : "l"(a), "l"(b));
}
__device__ __forceinline__ unsigned long long pack_dup(float a) {
    unsigned long long d; unsigned r = __float_as_uint(a);
    asm("mov.b64 %0, {%1, %1};" : "=l"(d) : "r"(r));
    return d;
}
__device__ __forceinline__ void unpack2(unsigned long long v, float& lo, float& hi) {
    unsigned l, h;
    asm("mov.b64 {%0, %1}, %2;" : "=r"(l), "=r"(h) : "l"(v));
    lo = __uint_as_float(l); hi = __uint_as_float(h);
}
__device__ __forceinline__ float sum2(unsigned long long v) {
    float lo, hi; unpack2(v, lo, hi); return lo + hi;
}

// ---------------- scratch (device globals; no cudaMalloc allowed) ----------------
__device__ float g_gi[(size_t)S_LEN * BATCH * G3H];   // 192 MiB, reused both layers
__device__ float g_out0[(size_t)S_LEN * BATCH * H];   // 64 MiB, layer-0 outputs
__device__ float g_h[4][BATCH * H];                   // h double-buffers, per layer
__device__ unsigned g_bar[8];                         // barrier counters (4 grp x 2 layer)
__device__ unsigned char g_mask[4][BATCH * H];        // canonical uint8 masks

// ---- fused: detect mask transport dtype (per-block, redundant) + convert all 4 ----
// masks concatenated: m0 (16384) | m1,m2,m3 (32768 each). dst layout fixed 32768 stride.
__global__ void convert_masks_kernel(const void* __restrict__ m0, const void* __restrict__ m1,
                                     const void* __restrict__ m2, const void* __restrict__ m3,
                                     unsigned char* __restrict__ dst) {
    // detect from first 1024 words of m0 (bool data -> distinctive bit patterns)
    int f_bf = 0, f_f32 = 0, f_up = 0;
    for (int i = threadIdx.x; i < 1024; i += 256) {
        unsigned w = ((const unsigned*)m0)[i];
        if ((w & 0xFFFFu) == 0x3F80u) f_bf = 1;
        if (w == 0x3F800000u)         f_f32 = 1;
        else if (w != 0u && (w & 0xFFFFFF00u) != 0u && (w & 0xFFFFu) != 0x3F80u) f_up = 1;
    }
    f_bf  = __syncthreads_or(f_bf);
    f_f32 = __syncthreads_or(f_f32);
    f_up  = __syncthreads_or(f_up);
    int code = f_bf ? 3 : (f_f32 ? 2 : (f_up ? 1 : 0)); // 0=int32 1=uint8 2=f32 3=bf16

    int gidx = blockIdx.x * 256 + threadIdx.x;          // 0 .. 114687
    const void* src; int si; unsigned char* d;
    if      (gidx < 16384) { src = m0; si = gidx;          d = dst + si; }
    else if (gidx < 49152) { src = m1; si = gidx - 16384;  d = dst + 32768  + si; }
    else if (gidx < 81920) { src = m2; si = gidx - 49152;  d = dst + 65536  + si; }
    else if (gidx < 114688){ src = m3; si = gidx - 81920;  d = dst + 98304  + si; }
    else return;
    unsigned char v;
    if      (code == 0) v = ((const int*)src)[si] != 0;
    else if (code == 1) v = ((const unsigned char*)src)[si] != 0;
    else if (code == 2) v = ((const float*)src)[si] != 0.f;
    else                v = ((const unsigned short*)src)[si] != 0;
    *d = v;
}

// zero all 4 h buffers + 8 barrier counters
__global__ void reset_kernel(float* hbase) {
    int i = blockIdx.x * blockDim.x + threadIdx.x;
    if (i < 8) g_bar[i] = 0u;
    if (i < 4 * BATCH * H) hbase[i] = 0.f;
}

__global__ void copy_kernel(const float* __restrict__ src, float* __restrict__ dst, int n) {
    int i = blockIdx.x * blockDim.x + threadIdx.x;
    if (i < n) dst[i] = src[i];
}

// ---- C[M][1536] = drop(A)[M][K] @ W[1536][K]^T + bias ----
// 128x128x8 tile, 256 threads, 8x8 microtile, f32x2-packed accumulation.
__global__ void __launch_bounds__(256) sgemm_mask_bias_kernel(
    const float* __restrict__ A, const unsigned char* __restrict__ mask,
    const float* __restrict__ W, const float* __restrict__ bias,
    float* __restrict__ C, int K)
{
    __shared__ float As[8][128];
    __shared__ float Bs[8][128];

    int tid = threadIdx.x;
    int tx = tid % 16;
    int ty = tid / 16;
    int row0 = blockIdx.y * 128;
    int col0 = blockIdx.x * 128;

    int la_r = tid >> 1;
    int la_c = (tid & 1) * 4;

    int arow = row0 + la_r;
    int b    = arow % BATCH;
    const float* Aptr = A + (size_t)arow * K + la_c;
    const unsigned char* Mptr = mask + (size_t)b * K + la_c;
    const float* Wptr = W + (size_t)(col0 + la_r) * K + la_c;

    unsigned long long acc2[8][4];
    #pragma unroll
    for (int i = 0; i < 8; i++)
        #pragma unroll
        for (int j = 0; j < 4; j++) acc2[i][j] = 0ull;

    for (int k0 = 0; k0 < K; k0 += 8) {
        float4 a4 = *(const float4*)(Aptr + k0);
        uchar4 m4 = *(const uchar4*)(Mptr + k0);
        float4 b4 = *(const float4*)(Wptr + k0);
        As[la_c + 0][la_r] = m4.x ? 0.f : a4.x * SCALE;
        As[la_c + 1][la_r] = m4.y ? 0.f : a4.y * SCALE;
        As[la_c + 2][la_r] = m4.z ? 0.f : a4.z * SCALE;
        As[la_c + 3][la_r] = m4.w ? 0.f : a4.w * SCALE;
        Bs[la_c + 0][la_r] = b4.x; Bs[la_c + 1][la_r] = b4.y;
        Bs[la_c + 2][la_r] = b4.z; Bs[la_c + 3][la_r] = b4.w;
        __syncthreads();
        #pragma unroll
        for (int k = 0; k < 8; k++) {
            float4 af0 = *(const float4*)&As[k][ty * 8];
            float4 af1 = *(const float4*)&As[k][ty * 8 + 4];
            ULL2 bb0 = *(const ULL2*)&Bs[k][tx * 8];
            ULL2 bb1 = *(const ULL2*)&Bs[k][tx * 8 + 4];
            float af[8] = {af0.x, af0.y, af0.z, af0.w, af1.x, af1.y, af1.z, af1.w};
            #pragma unroll
            for (int i = 0; i < 8; i++) {
                unsigned long long a2 = pack_dup(af[i]);
                ffma2(acc2[i][0], a2, bb0.x);
                ffma2(acc2[i][1], a2, bb0.y);
                ffma2(acc2[i][2], a2, bb1.x);
                ffma2(acc2[i][3], a2, bb1.y);
            }
        }
        __syncthreads();
    }

    #pragma unroll
    for (int i = 0; i < 8; i++) {
        int m = row0 + ty * 8 + i;
        int n = col0 + tx * 8;
        float4 v0, v1;
        unpack2(acc2[i][0], v0.x, v0.y);
        unpack2(acc2[i][1], v0.z, v0.w);
        unpack2(acc2[i][2], v1.x, v1.y);
        unpack2(acc2[i][3], v1.z, v1.w);
        v0.x += bias[n + 0]; v0.y += bias[n + 1];
        v0.z += bias[n + 2]; v0.w += bias[n + 3];
        v1.x += bias[n + 4]; v1.y += bias[n + 5];
        v1.z += bias[n + 6]; v1.w += bias[n + 7];
        *(float4*)&C[(size_t)m * G3H + n]     = v0;
        *(float4*)&C[(size_t)m * G3H + n + 4] = v1;
    }
}

// ---------------- persistent GRU layer: all 512 steps in one launch ----------------
// 128 blocks = 32 j-tiles (16 j) x 4 batch-groups (16 b).
// Per-block W slice = 16j x 3g x 512k x 4B = 98 KB -> L1-resident across steps.
// Warp = 64-k slice; lane = (j_local<<1)|k_half (thread covers 32 k).
// Pair-reduce via shfl, 8-warp reduce via smem. Group barrier = 32 CTAs.
// Dynamic smem: hd_s (16*H floats) | red_s (8*16*3*17 floats) = 58880 B.
__global__ void __launch_bounds__(256) gru_layer_kernel(
    float* __restrict__ h_a, float* __restrict__ h_b,
    const float* __restrict__ gi,            // [S][B][3H]
    const float* __restrict__ w_hh,          // [1536][512]
    const float* __restrict__ b_hh,          // [1536]
    const unsigned char* __restrict__ mask_h,// [B][H] canonical uint8
    float* __restrict__ out,                 // [S][B][H]
    int bar_base)
{
    extern __shared__ float smem_dyn[];
    float* hd_s = smem_dyn;                       // [16*H] 32 KB
    float (*red_s)[16][3][17] =
        (float (*)[16][3][17])(smem_dyn + 16 * H); // [8][16][3][17] 25.5 KB

    int tid  = threadIdx.x;
    int lane = tid & 31;
    int warp = tid >> 5;
    int jt   = blockIdx.x & 31;
    int grp  = blockIdx.x >> 5;                   // 0..3
    int jbase = jt * 16;
    int bbase = grp * 16;

    int jl = lane >> 1;                           // 0..15
    int kh = lane & 1;
    int j  = jbase + jl;
    int kbase = warp * 64 + kh * 32;              // 32-k slice per thread

    const ULL2* wr2 = (const ULL2*)(w_hh + ((size_t)(0 * H + j)) * H + kbase);
    const ULL2* wz2 = (const ULL2*)(w_hh + ((size_t)(1 * H + j)) * H + kbase);
    const ULL2* wn2 = (const ULL2*)(w_hh + ((size_t)(2 * H + j)) * H + kbase);

    // epilogue mapping: one thread per (b, j) output
    int ejl = tid & 15, eb = tid >> 4;            // eb 0..15
    int ej  = jbase + ejl;
    int ebg = bbase + eb;

    const uchar4* mrow4 = (const uchar4*)(mask_h + (size_t)bbase * H);

    unsigned target = 32u;

    for (int s = 0; s < S_LEN; s++) {
        const float* h_in  = (s & 1) ? h_b : h_a;
        float*       h_out = (s & 1) ? h_a : h_b;
        const float* gi_s  = gi  + (size_t)s * BATCH * G3H;
        float*       out_s = out + (size_t)s * BATCH * H;

        // stage dropped hidden for this group's 16 batches (h via L2: .cg)
        const float4* hrow4 = (const float4*)(h_in + (size_t)bbase * H);
        #pragma unroll 4
        for (int i = tid; i < 16 * H / 4; i += 256) {
            float4 h4 = __ldcg(hrow4 + i);
            uchar4 m4 = mrow4[i];
            hd_s[i * 4 + 0] = m4.x ? 0.f : h4.x * SCALE;
            hd_s[i * 4 + 1] = m4.y ? 0.f : h4.y * SCALE;
            hd_s[i * 4 + 2] = m4.z ? 0.f : h4.z * SCALE;
            hd_s[i * 4 + 3] = m4.w ? 0.f : h4.w * SCALE;
        }
        __syncthreads();

        unsigned long long acc[3][16];
        #pragma unroll
        for (int g = 0; g < 3; g++)
            #pragma unroll
            for (int b = 0; b < 16; b++) acc[g][b] = 0ull;

        #pragma unroll
        for (int q = 0; q < 8; q++) {
            ULL2 r2 = wr2[q];
            ULL2 z2 = wz2[q];
            ULL2 n2 = wn2[q];
            #pragma unroll
            for (int b = 0; b < 16; b++) {
                ULL2 h2 = *(const ULL2*)&hd_s[b * H + kbase + q * 4];
                ffma2(acc[0][b], h2.x, r2.x); ffma2(acc[0][b], h2.y, r2.y);
                ffma2(acc[1][b], h2.x, z2.x); ffma2(acc[1][b], h2.y, z2.y);
                ffma2(acc[2][b], h2.x, n2.x); ffma2(acc[2][b], h2.y, n2.y);
            }
        }

        // pair-reduce (k-halves) then publish to smem
        #pragma unroll
        for (int g = 0; g < 3; g++)
            #pragma unroll
            for (int b = 0; b < 16; b++) {
                float v = sum2(acc[g][b]);
                v += __shfl_xor_sync(0xFFFFFFFFu, v, 1);
                if (kh == 0) red_s[warp][jl][g][b] = v;
            }
        __syncthreads();

        // epilogue: thread (eb, ejl)
        {
            float sr = 0.f, sz = 0.f, sn = 0.f;
            #pragma unroll
            for (int w = 0; w < 8; w++) {
                sr += red_s[w][ejl][0][eb];
                sz += red_s[w][ejl][1][eb];
                sn += red_s[w][ejl][2][eb];
            }
            const float* gib = gi_s + (size_t)ebg * G3H;
            float gr = __ldcg(gib + ej);
            float gz = __ldcg(gib + H + ej);
            float gn = __ldcg(gib + 2 * H + ej);
            float r = 1.f / (1.f + expf(-(gr + sr + b_hh[ej])));
            float z = 1.f / (1.f + expf(-(gz + sz + b_hh[H + ej])));
            float n = tanhf(gn + r * (sn + b_hh[2 * H + ej]));
            float hd = hd_s[eb * H + ej];
            float hnew = (1.f - z) * n + z * hd;
            __stcg(&h_out[(size_t)ebg * H + ej], hnew);
            __stcg(&out_s[(size_t)ebg * H + ej], hnew);
        }

        // ---- group barrier (32 CTAs sharing this batch group) ----
        __threadfence();
        __syncthreads();
        if (tid == 0) {
            atomicAdd(&g_bar[bar_base + grp], 1u);
            while (*(volatile unsigned*)&g_bar[bar_base + grp] < target) { }
        }
        __syncthreads();
        target += 32u;
    }
}

// ---------------- launch ----------------
extern "C" void kernel_launch(void* const* d_in, const int* in_sizes, int n_in,
                              void* d_out, int out_size) {
    const float* x     = (const float*)d_in[0];
    const void*  min0  = d_in[1];
    const void*  mh0   = d_in[2];
    const void*  min1  = d_in[3];
    const void*  mh1   = d_in[4];
    const float* w_ih0 = (const float*)d_in[5];
    const float* w_hh0 = (const float*)d_in[6];
    const float* b_ih0 = (const float*)d_in[7];
    const float* b_hh0 = (const float*)d_in[8];
    const float* w_ih1 = (const float*)d_in[9];
    const float* w_hh1 = (const float*)d_in[10];
    const float* b_ih1 = (const float*)d_in[11];
    const float* b_hh1 = (const float*)d_in[12];
    float* out = (float*)d_out;

    float *gi, *out0, *hbuf;
    unsigned char* mbuf;
    cudaGetSymbolAddress((void**)&gi,   g_gi);
    cudaGetSymbolAddress((void**)&out0, g_out0);
    cudaGetSymbolAddress((void**)&hbuf, g_h);
    cudaGetSymbolAddress((void**)&mbuf, g_mask);
    const int BH = BATCH * H;                    // 32768
    unsigned char* cmin0 = mbuf;
    unsigned char* cmh0  = mbuf + 32768;
    unsigned char* cmin1 = mbuf + 65536;
    unsigned char* cmh1  = mbuf + 98304;

    const int M = S_LEN * BATCH;                 // 32768
    dim3 gemm_grid(G3H / 128, M / 128);          // (12, 256)

    // opt in to >48KB dynamic smem for the persistent kernel (idempotent)
    cudaFuncSetAttribute(gru_layer_kernel,
                         cudaFuncAttributeMaxDynamicSharedMemorySize, GRU_SMEM_BYTES);

    // 1: normalize all masks (fused detect + convert)
    convert_masks_kernel<<<448, 256>>>(min0, mh0, min1, mh1, mbuf);
    // 2: zero h buffers + barrier counters
    reset_kernel<<<(4 * BH + 255) / 256, 256>>>(hbuf);
    // 3-4: layer 0
    sgemm_mask_bias_kernel<<<gemm_grid, 256>>>(x, cmin0, w_ih0, b_ih0, gi, DIN);
    gru_layer_kernel<<<NBLK, 256, GRU_SMEM_BYTES>>>(hbuf, hbuf + BH, gi,
                                                    w_hh0, b_hh0, cmh0, out0, 0);
    // 5-6: layer 1
    sgemm_mask_bias_kernel<<<gemm_grid, 256>>>(out0, cmin1, w_ih1, b_ih1, gi, H);
    gru_layer_kernel<<<NBLK, 256, GRU_SMEM_BYTES>>>(hbuf + 2 * BH, hbuf + 3 * BH, gi,
                                                    w_hh1, b_hh1, cmh1, out, 4);
    // 7: h_last == out1[S-1]
    copy_kernel<<<(BH + 255) / 256, 256>>>(out + (size_t)(S_LEN - 1) * BH,
                                           out + (size_t)S_LEN * BH, BH);
}

// round 12
// speedup vs baseline: 1.5766x; 1.3397x over previous
#include <cuda_runtime.h>
#include <math.h>

#define S_LEN 512
#define BATCH 64
#define DIN   256
#define H     512
#define G3H   1536          // 3*H
#define SCALE 1.25f         // 1/(1-0.2)
#define NBLK  128           // persistent grid: 32 j-tiles x 4 batch-groups

#define GRU_SMEM_BYTES (16 * H * 4 + 8 * 3 * 16 * 17 * 4)   // 32768 + 26112 = 58880

// ---------------- packed f32x2 helpers (FFMA2: 2x fp32 per issue, IEEE-exact) ----
struct alignas(16) ULL2 { unsigned long long x, y; };

__device__ __forceinline__ void ffma2(unsigned long long& d,
                                      unsigned long long a, unsigned long long b) {
    asm("fma.rn.f32x2 %0, %1, %2, %0;" : "+l"(d) : "l"(a), "l"(b));
}
__device__ __forceinline__ unsigned long long pack_dup(float a) {
    unsigned long long d; unsigned r = __float_as_uint(a);
    asm("mov.b64 %0, {%1, %1};" : "=l"(d) : "r"(r));
    return d;
}
__device__ __forceinline__ void unpack2(unsigned long long v, float& lo, float& hi) {
    unsigned l, h;
    asm("mov.b64 {%0, %1}, %2;" : "=r"(l), "=r"(h) : "l"(v));
    lo = __uint_as_float(l); hi = __uint_as_float(h);
}
__device__ __forceinline__ float sum2(unsigned long long v) {
    float lo, hi; unpack2(v, lo, hi); return lo + hi;
}

// ---------------- scratch (device globals; no cudaMalloc allowed) ----------------
__device__ float g_gi[(size_t)S_LEN * BATCH * G3H];   // 192 MiB, reused both layers
__device__ float g_out0[(size_t)S_LEN * BATCH * H];   // 64 MiB, layer-0 outputs
__device__ float g_h[4][BATCH * H];                   // h double-buffers, per layer
__device__ float4 g_wt[3 * 512 * 128];                // 3 MiB transposed W_hh (per layer)
__device__ unsigned g_bar[8];                         // barrier counters (4 grp x 2 layer)
__device__ unsigned char g_mask[4][BATCH * H];        // canonical uint8 masks

// ---- fused: detect mask transport dtype (per-block, redundant) + convert all 4 ----
__global__ void convert_masks_kernel(const void* __restrict__ m0, const void* __restrict__ m1,
                                     const void* __restrict__ m2, const void* __restrict__ m3,
                                     unsigned char* __restrict__ dst) {
    int f_bf = 0, f_f32 = 0, f_up = 0;
    for (int i = threadIdx.x; i < 1024; i += 256) {
        unsigned w = ((const unsigned*)m0)[i];
        if ((w & 0xFFFFu) == 0x3F80u) f_bf = 1;
        if (w == 0x3F800000u)         f_f32 = 1;
        else if (w != 0u && (w & 0xFFFFFF00u) != 0u && (w & 0xFFFFu) != 0x3F80u) f_up = 1;
    }
    f_bf  = __syncthreads_or(f_bf);
    f_f32 = __syncthreads_or(f_f32);
    f_up  = __syncthreads_or(f_up);
    int code = f_bf ? 3 : (f_f32 ? 2 : (f_up ? 1 : 0)); // 0=int32 1=uint8 2=f32 3=bf16

    int gidx = blockIdx.x * 256 + threadIdx.x;          // 0 .. 114687
    const void* src; int si; unsigned char* d;
    if      (gidx < 16384) { src = m0; si = gidx;          d = dst + si; }
    else if (gidx < 49152) { src = m1; si = gidx - 16384;  d = dst + 32768  + si; }
    else if (gidx < 81920) { src = m2; si = gidx - 49152;  d = dst + 65536  + si; }
    else if (gidx < 114688){ src = m3; si = gidx - 81920;  d = dst + 98304  + si; }
    else return;
    unsigned char v;
    if      (code == 0) v = ((const int*)src)[si] != 0;
    else if (code == 1) v = ((const unsigned char*)src)[si] != 0;
    else if (code == 2) v = ((const float*)src)[si] != 0.f;
    else                v = ((const unsigned short*)src)[si] != 0;
    *d = v;
}

// zero all 4 h buffers + 8 barrier counters
__global__ void reset_kernel(float* hbase) {
    int i = blockIdx.x * blockDim.x + threadIdx.x;
    if (i < 8) g_bar[i] = 0u;
    if (i < 4 * BATCH * H) hbase[i] = 0.f;
}

__global__ void copy_kernel(const float* __restrict__ src, float* __restrict__ dst, int n) {
    int i = blockIdx.x * blockDim.x + threadIdx.x;
    if (i < n) dst[i] = src[i];
}

// ---- transpose W_hh [1536][512] -> Wt[jt 32][g 3][kq 128][jl 16] (float4 per k-quad) ----
__global__ void transpose_w_kernel(const float* __restrict__ w, float4* __restrict__ wt) {
    int idx = blockIdx.x * 256 + threadIdx.x;   // 0 .. 196607
    if (idx >= 3 * 512 * 128) return;
    int jl  = idx & 15;
    int kq  = (idx >> 4) & 127;
    int rem = idx >> 11;                        // 0..95 = jt*3 + g
    int g   = rem % 3;
    int jt  = rem / 3;
    int row = g * H + jt * 16 + jl;
    wt[idx] = *(const float4*)(w + (size_t)row * H + kq * 4);
}

// ---- C[M][1536] = drop(A)[M][K] @ W[1536][K]^T + bias ----
// 128x128x16 tile, 256 threads, 8x8 microtile, f32x2 FMA, double-buffered smem.
__global__ void __launch_bounds__(256, 2) sgemm_mask_bias_kernel(
    const float* __restrict__ A, const unsigned char* __restrict__ mask,
    const float* __restrict__ W, const float* __restrict__ bias,
    float* __restrict__ C, int K)
{
    __shared__ float As[2][16][132];    // +4 pad: bank spread, keeps 16B alignment
    __shared__ float Bs[2][16][132];

    int tid = threadIdx.x;
    int tx = tid % 16;
    int ty = tid / 16;
    int row0 = blockIdx.y * 128;
    int col0 = blockIdx.x * 128;

    int la_r = tid >> 1;          // 0..127 (m or n row)
    int la_c = (tid & 1) * 8;     // k offset 0 or 8

    int arow = row0 + la_r;
    int b    = arow % BATCH;
    const float* Aptr = A + (size_t)arow * K + la_c;
    const unsigned char* Mptr = mask + (size_t)b * K + la_c;
    const float* Wptr = W + (size_t)(col0 + la_r) * K + la_c;

    unsigned long long acc2[8][4];
    #pragma unroll
    for (int i = 0; i < 8; i++)
        #pragma unroll
        for (int j = 0; j < 4; j++) acc2[i][j] = 0ull;

    // preload tile 0
    {
        float4 a0 = *(const float4*)(Aptr);
        float4 a1 = *(const float4*)(Aptr + 4);
        uchar4 q0 = *(const uchar4*)(Mptr);
        uchar4 q1 = *(const uchar4*)(Mptr + 4);
        float4 b0 = *(const float4*)(Wptr);
        float4 b1 = *(const float4*)(Wptr + 4);
        As[0][la_c + 0][la_r] = q0.x ? 0.f : a0.x * SCALE;
        As[0][la_c + 1][la_r] = q0.y ? 0.f : a0.y * SCALE;
        As[0][la_c + 2][la_r] = q0.z ? 0.f : a0.z * SCALE;
        As[0][la_c + 3][la_r] = q0.w ? 0.f : a0.w * SCALE;
        As[0][la_c + 4][la_r] = q1.x ? 0.f : a1.x * SCALE;
        As[0][la_c + 5][la_r] = q1.y ? 0.f : a1.y * SCALE;
        As[0][la_c + 6][la_r] = q1.z ? 0.f : a1.z * SCALE;
        As[0][la_c + 7][la_r] = q1.w ? 0.f : a1.w * SCALE;
        Bs[0][la_c + 0][la_r] = b0.x; Bs[0][la_c + 1][la_r] = b0.y;
        Bs[0][la_c + 2][la_r] = b0.z; Bs[0][la_c + 3][la_r] = b0.w;
        Bs[0][la_c + 4][la_r] = b1.x; Bs[0][la_c + 5][la_r] = b1.y;
        Bs[0][la_c + 6][la_r] = b1.z; Bs[0][la_c + 7][la_r] = b1.w;
    }
    __syncthreads();

    int nt = K / 16;
    for (int t = 0; t < nt; t++) {
        int cur = t & 1, nxt = cur ^ 1;
        float4 pa0, pa1, pb0, pb1; uchar4 pq0, pq1;
        if (t + 1 < nt) {
            int ko = (t + 1) * 16;
            pa0 = *(const float4*)(Aptr + ko);
            pa1 = *(const float4*)(Aptr + ko + 4);
            pq0 = *(const uchar4*)(Mptr + ko);
            pq1 = *(const uchar4*)(Mptr + ko + 4);
            pb0 = *(const float4*)(Wptr + ko);
            pb1 = *(const float4*)(Wptr + ko + 4);
        }
        #pragma unroll
        for (int k = 0; k < 16; k++) {
            float4 af0 = *(const float4*)&As[cur][k][ty * 8];
            float4 af1 = *(const float4*)&As[cur][k][ty * 8 + 4];
            ULL2 bb0 = *(const ULL2*)&Bs[cur][k][tx * 8];
            ULL2 bb1 = *(const ULL2*)&Bs[cur][k][tx * 8 + 4];
            float af[8] = {af0.x, af0.y, af0.z, af0.w, af1.x, af1.y, af1.z, af1.w};
            #pragma unroll
            for (int i = 0; i < 8; i++) {
                unsigned long long a2 = pack_dup(af[i]);
                ffma2(acc2[i][0], a2, bb0.x);
                ffma2(acc2[i][1], a2, bb0.y);
                ffma2(acc2[i][2], a2, bb1.x);
                ffma2(acc2[i][3], a2, bb1.y);
            }
        }
        if (t + 1 < nt) {
            As[nxt][la_c + 0][la_r] = pq0.x ? 0.f : pa0.x * SCALE;
            As[nxt][la_c + 1][la_r] = pq0.y ? 0.f : pa0.y * SCALE;
            As[nxt][la_c + 2][la_r] = pq0.z ? 0.f : pa0.z * SCALE;
            As[nxt][la_c + 3][la_r] = pq0.w ? 0.f : pa0.w * SCALE;
            As[nxt][la_c + 4][la_r] = pq1.x ? 0.f : pa1.x * SCALE;
            As[nxt][la_c + 5][la_r] = pq1.y ? 0.f : pa1.y * SCALE;
            As[nxt][la_c + 6][la_r] = pq1.z ? 0.f : pa1.z * SCALE;
            As[nxt][la_c + 7][la_r] = pq1.w ? 0.f : pa1.w * SCALE;
            Bs[nxt][la_c + 0][la_r] = pb0.x; Bs[nxt][la_c + 1][la_r] = pb0.y;
            Bs[nxt][la_c + 2][la_r] = pb0.z; Bs[nxt][la_c + 3][la_r] = pb0.w;
            Bs[nxt][la_c + 4][la_r] = pb1.x; Bs[nxt][la_c + 5][la_r] = pb1.y;
            Bs[nxt][la_c + 6][la_r] = pb1.z; Bs[nxt][la_c + 7][la_r] = pb1.w;
        }
        __syncthreads();
    }

    #pragma unroll
    for (int i = 0; i < 8; i++) {
        int m = row0 + ty * 8 + i;
        int n = col0 + tx * 8;
        float4 v0, v1;
        unpack2(acc2[i][0], v0.x, v0.y);
        unpack2(acc2[i][1], v0.z, v0.w);
        unpack2(acc2[i][2], v1.x, v1.y);
        unpack2(acc2[i][3], v1.z, v1.w);
        v0.x += bias[n + 0]; v0.y += bias[n + 1];
        v0.z += bias[n + 2]; v0.w += bias[n + 3];
        v1.x += bias[n + 4]; v1.y += bias[n + 5];
        v1.z += bias[n + 6]; v1.w += bias[n + 7];
        *(float4*)&C[(size_t)m * G3H + n]     = v0;
        *(float4*)&C[(size_t)m * G3H + n + 4] = v1;
    }
}

// ---------------- persistent GRU layer: all 512 steps in one launch ----------------
// 128 blocks = 32 j-tiles (16 j) x 4 batch-groups (16 b). 512 threads (16 warps).
// warp w: bh = w&1 (8-batch half), kw = w>>1 (64-k slice).
// lane: jl = lane>>1 (j within tile), kh = lane&1 (k-quad parity).
// Thread covers 8 interleaved k-quads (32 k) for 1 j x 8 b x 3 gates.
// W read from transposed Wt[jt][g][kq][jl] -> warp-coalesced 4-line loads.
__global__ void __launch_bounds__(512) gru_layer_kernel(
    float* __restrict__ h_a, float* __restrict__ h_b,
    const float* __restrict__ gi,            // [S][B][3H]
    const float4* __restrict__ wt,           // transposed W_hh
    const float* __restrict__ b_hh,          // [1536]
    const unsigned char* __restrict__ mask_h,// [B][H] canonical uint8
    float* __restrict__ out,                 // [S][B][H]
    int bar_base)
{
    extern __shared__ float smem_dyn[];
    float* hd_s = smem_dyn;                        // [16*H] 32 KB
    float (*red_s)[3][16][17] =
        (float (*)[3][16][17])(smem_dyn + 16 * H); // [8 kw][3 g][16 b][17] 25.5 KB

    int tid  = threadIdx.x;
    int lane = tid & 31;
    int warp = tid >> 5;
    int jt   = blockIdx.x & 31;
    int grp  = blockIdx.x >> 5;                    // 0..3
    int bbase = grp * 16;

    int bh = warp & 1;                             // batch half (8 b)
    int kw = warp >> 1;                            // 0..7 (64-k slice)
    int jl = lane >> 1;                            // 0..15
    int kh = lane & 1;
    int kwq = kw * 16;                             // first k-quad of slice

    // W pointers (float4 per k-quad), stride 32 float4 per q step
    const float4* wp0 = wt + (((size_t)(jt * 3 + 0) * 128) + kwq + kh) * 16 + jl;
    const float4* wp1 = wt + (((size_t)(jt * 3 + 1) * 128) + kwq + kh) * 16 + jl;
    const float4* wp2 = wt + (((size_t)(jt * 3 + 2) * 128) + kwq + kh) * 16 + jl;

    // epilogue mapping: threads 0..255 -> one (b, j) output each
    int ejl = tid & 15, eb = (tid >> 4) & 15;
    int ej  = jt * 16 + ejl;
    int ebg = bbase + eb;
    float brc = b_hh[ej], bzc = b_hh[H + ej], bnc = b_hh[2 * H + ej];

    const uchar4* mrow4 = (const uchar4*)(mask_h + (size_t)bbase * H);

    unsigned target = 32u;

    for (int s = 0; s < S_LEN; s++) {
        const float* h_in  = (s & 1) ? h_b : h_a;
        float*       h_out = (s & 1) ? h_a : h_b;
        const float* gi_s  = gi  + (size_t)s * BATCH * G3H;
        float*       out_s = out + (size_t)s * BATCH * H;

        // stage dropped hidden for this group's 16 batches (h via L2: .cg)
        const float4* hrow4 = (const float4*)(h_in + (size_t)bbase * H);
        #pragma unroll
        for (int i = tid; i < 16 * H / 4; i += 512) {
            float4 h4 = __ldcg(hrow4 + i);
            uchar4 m4 = mrow4[i];
            hd_s[i * 4 + 0] = m4.x ? 0.f : h4.x * SCALE;
            hd_s[i * 4 + 1] = m4.y ? 0.f : h4.y * SCALE;
            hd_s[i * 4 + 2] = m4.z ? 0.f : h4.z * SCALE;
            hd_s[i * 4 + 3] = m4.w ? 0.f : h4.w * SCALE;
        }
        __syncthreads();

        unsigned long long acc[3][8];
        #pragma unroll
        for (int g = 0; g < 3; g++)
            #pragma unroll
            for (int b = 0; b < 8; b++) acc[g][b] = 0ull;

        #pragma unroll
        for (int q = 0; q < 8; q++) {
            ULL2 w0 = *(const ULL2*)(wp0 + 32 * q);
            ULL2 w1 = *(const ULL2*)(wp1 + 32 * q);
            ULL2 w2 = *(const ULL2*)(wp2 + 32 * q);
            int koff = (kwq + kh + 2 * q) * 4;
            #pragma unroll
            for (int b = 0; b < 8; b++) {
                ULL2 h2 = *(const ULL2*)&hd_s[(bh * 8 + b) * H + koff];
                ffma2(acc[0][b], h2.x, w0.x); ffma2(acc[0][b], h2.y, w0.y);
                ffma2(acc[1][b], h2.x, w1.x); ffma2(acc[1][b], h2.y, w1.y);
                ffma2(acc[2][b], h2.x, w2.x); ffma2(acc[2][b], h2.y, w2.y);
            }
        }

        // kh-pair reduce via shfl, publish per-kw partials to smem
        #pragma unroll
        for (int g = 0; g < 3; g++)
            #pragma unroll
            for (int b = 0; b < 8; b++) {
                float v = sum2(acc[g][b]);
                v += __shfl_xor_sync(0xFFFFFFFFu, v, 1);
                if (kh == 0) red_s[kw][g][bh * 8 + b][jl] = v;
            }
        __syncthreads();

        // epilogue: threads 0..255, one (b, j) each; sum 8 kw partials
        if (tid < 256) {
            float sr = 0.f, sz = 0.f, sn = 0.f;
            #pragma unroll
            for (int w = 0; w < 8; w++) {
                sr += red_s[w][0][eb][ejl];
                sz += red_s[w][1][eb][ejl];
                sn += red_s[w][2][eb][ejl];
            }
            const float* gib = gi_s + (size_t)ebg * G3H;
            float gr = __ldcg(gib + ej);
            float gz = __ldcg(gib + H + ej);
            float gn = __ldcg(gib + 2 * H + ej);
            float r = 1.f / (1.f + expf(-(gr + sr + brc)));
            float z = 1.f / (1.f + expf(-(gz + sz + bzc)));
            float n = tanhf(gn + r * (sn + bnc));
            float hd = hd_s[eb * H + ej];
            float hnew = (1.f - z) * n + z * hd;
            __stcg(&h_out[(size_t)ebg * H + ej], hnew);
            __stcg(&out_s[(size_t)ebg * H + ej], hnew);
        }

        // ---- group barrier (32 CTAs sharing this batch group) ----
        __threadfence();
        __syncthreads();
        if (tid == 0) {
            atomicAdd(&g_bar[bar_base + grp], 1u);
            while (*(volatile unsigned*)&g_bar[bar_base + grp] < target) { }
        }
        __syncthreads();
        target += 32u;
    }
}

// ---------------- launch ----------------
extern "C" void kernel_launch(void* const* d_in, const int* in_sizes, int n_in,
                              void* d_out, int out_size) {
    const float* x     = (const float*)d_in[0];
    const void*  min0  = d_in[1];
    const void*  mh0   = d_in[2];
    const void*  min1  = d_in[3];
    const void*  mh1   = d_in[4];
    const float* w_ih0 = (const float*)d_in[5];
    const float* w_hh0 = (const float*)d_in[6];
    const float* b_ih0 = (const float*)d_in[7];
    const float* b_hh0 = (const float*)d_in[8];
    const float* w_ih1 = (const float*)d_in[9];
    const float* w_hh1 = (const float*)d_in[10];
    const float* b_ih1 = (const float*)d_in[11];
    const float* b_hh1 = (const float*)d_in[12];
    float* out = (float*)d_out;

    float *gi, *out0, *hbuf;
    float4* wt;
    unsigned char* mbuf;
    cudaGetSymbolAddress((void**)&gi,   g_gi);
    cudaGetSymbolAddress((void**)&out0, g_out0);
    cudaGetSymbolAddress((void**)&hbuf, g_h);
    cudaGetSymbolAddress((void**)&wt,   g_wt);
    cudaGetSymbolAddress((void**)&mbuf, g_mask);
    const int BH = BATCH * H;                    // 32768
    unsigned char* cmin0 = mbuf;
    unsigned char* cmh0  = mbuf + 32768;
    unsigned char* cmin1 = mbuf + 65536;
    unsigned char* cmh1  = mbuf + 98304;

    const int M = S_LEN * BATCH;                 // 32768
    dim3 gemm_grid(G3H / 128, M / 128);          // (12, 256)

    cudaFuncSetAttribute(gru_layer_kernel,
                         cudaFuncAttributeMaxDynamicSharedMemorySize, GRU_SMEM_BYTES);

    // 1: normalize all masks (fused detect + convert)
    convert_masks_kernel<<<448, 256>>>(min0, mh0, min1, mh1, mbuf);
    // 2: zero h buffers + barrier counters
    reset_kernel<<<(4 * BH + 255) / 256, 256>>>(hbuf);
    // layer 0
    transpose_w_kernel<<<768, 256>>>(w_hh0, wt);
    sgemm_mask_bias_kernel<<<gemm_grid, 256>>>(x, cmin0, w_ih0, b_ih0, gi, DIN);
    gru_layer_kernel<<<NBLK, 512, GRU_SMEM_BYTES>>>(hbuf, hbuf + BH, gi,
                                                    wt, b_hh0, cmh0, out0, 0);
    // layer 1
    transpose_w_kernel<<<768, 256>>>(w_hh1, wt);
    sgemm_mask_bias_kernel<<<gemm_grid, 256>>>(out0, cmin1, w_ih1, b_ih1, gi, H);
    gru_layer_kernel<<<NBLK, 512, GRU_SMEM_BYTES>>>(hbuf + 2 * BH, hbuf + 3 * BH, gi,
                                                    wt, b_hh1, cmh1, out, 4);
    // h_last == out1[S-1]
    copy_kernel<<<(BH + 255) / 256, 256>>>(out + (size_t)(S_LEN - 1) * BH,
                                           out + (size_t)S_LEN * BH, BH);
}

// round 14
// speedup vs baseline: 1.7751x; 1.1259x over previous
#include <cuda_runtime.h>
#include <math.h>

#define S_LEN 512
#define BATCH 64
#define DIN   256
#define H     512
#define G3H   1536          // 3*H
#define SCALE 1.25f         // 1/(1-0.2)
#define NBLK  128           // persistent grid: 32 j-tiles x 4 batch-groups

// dynamic smem: W slice (3*128*16 float4 = 98304 B) + hd (32768 B) + red (26112 B)
#define W_SMEM_F4   (3 * 128 * 16)
#define GRU_SMEM_BYTES (W_SMEM_F4 * 16 + 16 * H * 4 + 8 * 3 * 16 * 17 * 4)  // 157184

// ---------------- packed f32x2 helpers (FFMA2: 2x fp32 per issue, IEEE-exact) ----
struct alignas(16) ULL2 { unsigned long long x, y; };

__device__ __forceinline__ void ffma2(unsigned long long& d,
                                      unsigned long long a, unsigned long long b) {
    asm("fma.rn.f32x2 %0, %1, %2, %0;" : "+l"(d) : "l"(a), "l"(b));
}
__device__ __forceinline__ unsigned long long pack_dup(float a) {
    unsigned long long d; unsigned r = __float_as_uint(a);
    asm("mov.b64 %0, {%1, %1};" : "=l"(d) : "r"(r));
    return d;
}
__device__ __forceinline__ void unpack2(unsigned long long v, float& lo, float& hi) {
    unsigned l, h;
    asm("mov.b64 {%0, %1}, %2;" : "=r"(l), "=r"(h) : "l"(v));
    lo = __uint_as_float(l); hi = __uint_as_float(h);
}
__device__ __forceinline__ float sum2(unsigned long long v) {
    float lo, hi; unpack2(v, lo, hi); return lo + hi;
}

// ---- barrier ops WITHOUT fence instructions (no CCTL.IVALL -> L1 stays warm) ----
__device__ __forceinline__ void bar_arrive_release(unsigned* p) {
    unsigned one = 1u;
    asm volatile("red.release.gpu.global.add.u32 [%0], %1;" :: "l"(p), "r"(one) : "memory");
}
__device__ __forceinline__ unsigned bar_poll_acquire(unsigned* p) {
    unsigned v;
    asm volatile("ld.acquire.gpu.global.u32 %0, [%1];" : "=r"(v) : "l"(p) : "memory");
    return v;
}

// ---------------- scratch (device globals; no cudaMalloc allowed) ----------------
__device__ float g_gi[(size_t)S_LEN * BATCH * G3H];   // 192 MiB, reused both layers
__device__ float g_out0[(size_t)S_LEN * BATCH * H];   // 64 MiB, layer-0 outputs
__device__ float g_h[4][BATCH * H];                   // h double-buffers, per layer
__device__ float4 g_wt[3 * 512 * 128];                // 3 MiB transposed W_hh (per layer)
__device__ unsigned g_bar[8];                         // barrier counters (4 grp x 2 layer)
__device__ unsigned char g_mask[4][BATCH * H];        // canonical uint8 masks

// ---- fused: detect mask transport dtype (per-block, redundant) + convert all 4 ----
__global__ void convert_masks_kernel(const void* __restrict__ m0, const void* __restrict__ m1,
                                     const void* __restrict__ m2, const void* __restrict__ m3,
                                     unsigned char* __restrict__ dst) {
    int f_bf = 0, f_f32 = 0, f_up = 0;
    for (int i = threadIdx.x; i < 1024; i += 256) {
        unsigned w = ((const unsigned*)m0)[i];
        if ((w & 0xFFFFu) == 0x3F80u) f_bf = 1;
        if (w == 0x3F800000u)         f_f32 = 1;
        else if (w != 0u && (w & 0xFFFFFF00u) != 0u && (w & 0xFFFFu) != 0x3F80u) f_up = 1;
    }
    f_bf  = __syncthreads_or(f_bf);
    f_f32 = __syncthreads_or(f_f32);
    f_up  = __syncthreads_or(f_up);
    int code = f_bf ? 3 : (f_f32 ? 2 : (f_up ? 1 : 0)); // 0=int32 1=uint8 2=f32 3=bf16

    int gidx = blockIdx.x * 256 + threadIdx.x;          // 0 .. 114687
    const void* src; int si; unsigned char* d;
    if      (gidx < 16384) { src = m0; si = gidx;          d = dst + si; }
    else if (gidx < 49152) { src = m1; si = gidx - 16384;  d = dst + 32768  + si; }
    else if (gidx < 81920) { src = m2; si = gidx - 49152;  d = dst + 65536  + si; }
    else if (gidx < 114688){ src = m3; si = gidx - 81920;  d = dst + 98304  + si; }
    else return;
    unsigned char v;
    if      (code == 0) v = ((const int*)src)[si] != 0;
    else if (code == 1) v = ((const unsigned char*)src)[si] != 0;
    else if (code == 2) v = ((const float*)src)[si] != 0.f;
    else                v = ((const unsigned short*)src)[si] != 0;
    *d = v;
}

// zero all 4 h buffers + 8 barrier counters
__global__ void reset_kernel(float* hbase) {
    int i = blockIdx.x * blockDim.x + threadIdx.x;
    if (i < 8) g_bar[i] = 0u;
    if (i < 4 * BATCH * H) hbase[i] = 0.f;
}

__global__ void copy_kernel(const float* __restrict__ src, float* __restrict__ dst, int n) {
    int i = blockIdx.x * blockDim.x + threadIdx.x;
    if (i < n) dst[i] = src[i];
}

// ---- transpose W_hh [1536][512] -> Wt[jt 32][g 3][kq 128][jl 16] (float4 per k-quad) ----
__global__ void transpose_w_kernel(const float* __restrict__ w, float4* __restrict__ wt) {
    int idx = blockIdx.x * 256 + threadIdx.x;   // 0 .. 196607
    if (idx >= 3 * 512 * 128) return;
    int jl  = idx & 15;
    int kq  = (idx >> 4) & 127;
    int rem = idx >> 11;                        // 0..95 = jt*3 + g
    int g   = rem % 3;
    int jt  = rem / 3;
    int row = g * H + jt * 16 + jl;
    wt[idx] = *(const float4*)(w + (size_t)row * H + kq * 4);
}

// ---- C[M][1536] = drop(A)[M][K] @ W[1536][K]^T + bias ----
// 128x128x16 tile, 256 threads, 8x8 microtile, f32x2 FMA, double-buffered smem.
__global__ void __launch_bounds__(256, 2) sgemm_mask_bias_kernel(
    const float* __restrict__ A, const unsigned char* __restrict__ mask,
    const float* __restrict__ W, const float* __restrict__ bias,
    float* __restrict__ C, int K)
{
    __shared__ float As[2][16][132];    // +4 pad: bank spread, keeps 16B alignment
    __shared__ float Bs[2][16][132];

    int tid = threadIdx.x;
    int tx = tid % 16;
    int ty = tid / 16;
    int row0 = blockIdx.y * 128;
    int col0 = blockIdx.x * 128;

    int la_r = tid >> 1;          // 0..127 (m or n row)
    int la_c = (tid & 1) * 8;     // k offset 0 or 8

    int arow = row0 + la_r;
    int b    = arow % BATCH;
    const float* Aptr = A + (size_t)arow * K + la_c;
    const unsigned char* Mptr = mask + (size_t)b * K + la_c;
    const float* Wptr = W + (size_t)(col0 + la_r) * K + la_c;

    unsigned long long acc2[8][4];
    #pragma unroll
    for (int i = 0; i < 8; i++)
        #pragma unroll
        for (int j = 0; j < 4; j++) acc2[i][j] = 0ull;

    // preload tile 0
    {
        float4 a0 = *(const float4*)(Aptr);
        float4 a1 = *(const float4*)(Aptr + 4);
        uchar4 q0 = *(const uchar4*)(Mptr);
        uchar4 q1 = *(const uchar4*)(Mptr + 4);
        float4 b0 = *(const float4*)(Wptr);
        float4 b1 = *(const float4*)(Wptr + 4);
        As[0][la_c + 0][la_r] = q0.x ? 0.f : a0.x * SCALE;
        As[0][la_c + 1][la_r] = q0.y ? 0.f : a0.y * SCALE;
        As[0][la_c + 2][la_r] = q0.z ? 0.f : a0.z * SCALE;
        As[0][la_c + 3][la_r] = q0.w ? 0.f : a0.w * SCALE;
        As[0][la_c + 4][la_r] = q1.x ? 0.f : a1.x * SCALE;
        As[0][la_c + 5][la_r] = q1.y ? 0.f : a1.y * SCALE;
        As[0][la_c + 6][la_r] = q1.z ? 0.f : a1.z * SCALE;
        As[0][la_c + 7][la_r] = q1.w ? 0.f : a1.w * SCALE;
        Bs[0][la_c + 0][la_r] = b0.x; Bs[0][la_c + 1][la_r] = b0.y;
        Bs[0][la_c + 2][la_r] = b0.z; Bs[0][la_c + 3][la_r] = b0.w;
        Bs[0][la_c + 4][la_r] = b1.x; Bs[0][la_c + 5][la_r] = b1.y;
        Bs[0][la_c + 6][la_r] = b1.z; Bs[0][la_c + 7][la_r] = b1.w;
    }
    __syncthreads();

    int nt = K / 16;
    for (int t = 0; t < nt; t++) {
        int cur = t & 1, nxt = cur ^ 1;
        float4 pa0, pa1, pb0, pb1; uchar4 pq0, pq1;
        if (t + 1 < nt) {
            int ko = (t + 1) * 16;
            pa0 = *(const float4*)(Aptr + ko);
            pa1 = *(const float4*)(Aptr + ko + 4);
            pq0 = *(const uchar4*)(Mptr + ko);
            pq1 = *(const uchar4*)(Mptr + ko + 4);
            pb0 = *(const float4*)(Wptr + ko);
            pb1 = *(const float4*)(Wptr + ko + 4);
        }
        #pragma unroll
        for (int k = 0; k < 16; k++) {
            float4 af0 = *(const float4*)&As[cur][k][ty * 8];
            float4 af1 = *(const float4*)&As[cur][k][ty * 8 + 4];
            ULL2 bb0 = *(const ULL2*)&Bs[cur][k][tx * 8];
            ULL2 bb1 = *(const ULL2*)&Bs[cur][k][tx * 8 + 4];
            float af[8] = {af0.x, af0.y, af0.z, af0.w, af1.x, af1.y, af1.z, af1.w};
            #pragma unroll
            for (int i = 0; i < 8; i++) {
                unsigned long long a2 = pack_dup(af[i]);
                ffma2(acc2[i][0], a2, bb0.x);
                ffma2(acc2[i][1], a2, bb0.y);
                ffma2(acc2[i][2], a2, bb1.x);
                ffma2(acc2[i][3], a2, bb1.y);
            }
        }
        if (t + 1 < nt) {
            As[nxt][la_c + 0][la_r] = pq0.x ? 0.f : pa0.x * SCALE;
            As[nxt][la_c + 1][la_r] = pq0.y ? 0.f : pa0.y * SCALE;
            As[nxt][la_c + 2][la_r] = pq0.z ? 0.f : pa0.z * SCALE;
            As[nxt][la_c + 3][la_r] = pq0.w ? 0.f : pa0.w * SCALE;
            As[nxt][la_c + 4][la_r] = pq1.x ? 0.f : pa1.x * SCALE;
            As[nxt][la_c + 5][la_r] = pq1.y ? 0.f : pa1.y * SCALE;
            As[nxt][la_c + 6][la_r] = pq1.z ? 0.f : pa1.z * SCALE;
            As[nxt][la_c + 7][la_r] = pq1.w ? 0.f : pa1.w * SCALE;
            Bs[nxt][la_c + 0][la_r] = pb0.x; Bs[nxt][la_c + 1][la_r] = pb0.y;
            Bs[nxt][la_c + 2][la_r] = pb0.z; Bs[nxt][la_c + 3][la_r] = pb0.w;
            Bs[nxt][la_c + 4][la_r] = pb1.x; Bs[nxt][la_c + 5][la_r] = pb1.y;
            Bs[nxt][la_c + 6][la_r] = pb1.z; Bs[nxt][la_c + 7][la_r] = pb1.w;
        }
        __syncthreads();
    }

    #pragma unroll
    for (int i = 0; i < 8; i++) {
        int m = row0 + ty * 8 + i;
        int n = col0 + tx * 8;
        float4 v0, v1;
        unpack2(acc2[i][0], v0.x, v0.y);
        unpack2(acc2[i][1], v0.z, v0.w);
        unpack2(acc2[i][2], v1.x, v1.y);
        unpack2(acc2[i][3], v1.z, v1.w);
        v0.x += bias[n + 0]; v0.y += bias[n + 1];
        v0.z += bias[n + 2]; v0.w += bias[n + 3];
        v1.x += bias[n + 4]; v1.y += bias[n + 5];
        v1.z += bias[n + 6]; v1.w += bias[n + 7];
        *(float4*)&C[(size_t)m * G3H + n]     = v0;
        *(float4*)&C[(size_t)m * G3H + n + 4] = v1;
    }
}

// ---------------- persistent GRU layer: all 512 steps in one launch ----------------
// 128 blocks = 32 j-tiles (16 j) x 4 batch-groups (16 b). 512 threads (16 warps).
// W slice (98 KB) is copied to SMEM once; per-step reads are conflict-free LDS
// (immune to L1 flushes). Barrier uses release/acquire atomics -> NO fence insn
// -> no CCTL.IVALL -> gi/mask stay L1-resident.
__global__ void __launch_bounds__(512) gru_layer_kernel(
    float* __restrict__ h_a, float* __restrict__ h_b,
    const float* __restrict__ gi,            // [S][B][3H]
    const float4* __restrict__ wt,           // transposed W_hh
    const float* __restrict__ b_hh,          // [1536]
    const unsigned char* __restrict__ mask_h,// [B][H] canonical uint8
    float* __restrict__ out,                 // [S][B][H]
    unsigned* __restrict__ bar)              // per-group barrier counter base
{
    extern __shared__ float smem_dyn[];
    float4* w_s = (float4*)smem_dyn;                       // [3*128*16] 96 KB
    float*  hd_s = smem_dyn + W_SMEM_F4 * 4;               // [16*H] 32 KB
    float (*red_s)[3][16][17] =
        (float (*)[3][16][17])(hd_s + 16 * H);             // [8][3][16][17] 25.5 KB

    int tid  = threadIdx.x;
    int lane = tid & 31;
    int warp = tid >> 5;
    int jt   = blockIdx.x & 31;
    int grp  = blockIdx.x >> 5;                    // 0..3
    int bbase = grp * 16;

    int bh = warp & 1;                             // batch half (8 b)
    int kw = warp >> 1;                            // 0..7 (64-k slice)
    int jl = lane >> 1;                            // 0..15
    int kh = lane & 1;
    int kwq = kw * 16;                             // first k-quad of slice

    // copy this j-tile's W slice (6144 float4) into smem once
    {
        const float4* wsrc = wt + (size_t)jt * 3 * 128 * 16;
        for (int i = tid; i < W_SMEM_F4; i += 512)
            w_s[i] = wsrc[i];
    }

    // smem W pointers (float4 units), stride 32 float4 per q step
    const float4* wp0 = w_s + ((0 * 128) + kwq + kh) * 16 + jl;
    const float4* wp1 = w_s + ((1 * 128) + kwq + kh) * 16 + jl;
    const float4* wp2 = w_s + ((2 * 128) + kwq + kh) * 16 + jl;

    // epilogue mapping: threads 0..255 -> one (b, j) output each
    int ejl = tid & 15, eb = (tid >> 4) & 15;
    int ej  = jt * 16 + ejl;
    int ebg = bbase + eb;
    float brc = b_hh[ej], bzc = b_hh[H + ej], bnc = b_hh[2 * H + ej];

    const uchar4* mrow4 = (const uchar4*)(mask_h + (size_t)bbase * H);

    unsigned target = 32u;
    unsigned* mybar = bar + grp;

    __syncthreads();   // W slice visible

    for (int s = 0; s < S_LEN; s++) {
        const float* h_in  = (s & 1) ? h_b : h_a;
        float*       h_out = (s & 1) ? h_a : h_b;
        const float* gi_s  = gi  + (size_t)s * BATCH * G3H;
        float*       out_s = out + (size_t)s * BATCH * H;

        // prefetch gi gates for this thread's output (hidden under staging+compute)
        float gr = 0.f, gz = 0.f, gn = 0.f;
        if (tid < 256) {
            const float* gib = gi_s + (size_t)ebg * G3H;
            gr = __ldcg(gib + ej);
            gz = __ldcg(gib + H + ej);
            gn = __ldcg(gib + 2 * H + ej);
        }

        // stage dropped hidden for this group's 16 batches (h via L2: .cg)
        const float4* hrow4 = (const float4*)(h_in + (size_t)bbase * H);
        #pragma unroll
        for (int i = tid; i < 16 * H / 4; i += 512) {
            float4 h4 = __ldcg(hrow4 + i);
            uchar4 m4 = mrow4[i];
            hd_s[i * 4 + 0] = m4.x ? 0.f : h4.x * SCALE;
            hd_s[i * 4 + 1] = m4.y ? 0.f : h4.y * SCALE;
            hd_s[i * 4 + 2] = m4.z ? 0.f : h4.z * SCALE;
            hd_s[i * 4 + 3] = m4.w ? 0.f : h4.w * SCALE;
        }
        __syncthreads();

        unsigned long long acc[3][8];
        #pragma unroll
        for (int g = 0; g < 3; g++)
            #pragma unroll
            for (int b = 0; b < 8; b++) acc[g][b] = 0ull;

        #pragma unroll
        for (int q = 0; q < 8; q++) {
            ULL2 w0 = *(const ULL2*)(wp0 + 32 * q);
            ULL2 w1 = *(const ULL2*)(wp1 + 32 * q);
            ULL2 w2 = *(const ULL2*)(wp2 + 32 * q);
            int koff = (kwq + kh + 2 * q) * 4;
            #pragma unroll
            for (int b = 0; b < 8; b++) {
                ULL2 h2 = *(const ULL2*)&hd_s[(bh * 8 + b) * H + koff];
                ffma2(acc[0][b], h2.x, w0.x); ffma2(acc[0][b], h2.y, w0.y);
                ffma2(acc[1][b], h2.x, w1.x); ffma2(acc[1][b], h2.y, w1.y);
                ffma2(acc[2][b], h2.x, w2.x); ffma2(acc[2][b], h2.y, w2.y);
            }
        }

        // kh-pair reduce via shfl, publish per-kw partials to smem
        #pragma unroll
        for (int g = 0; g < 3; g++)
            #pragma unroll
            for (int b = 0; b < 8; b++) {
                float v = sum2(acc[g][b]);
                v += __shfl_xor_sync(0xFFFFFFFFu, v, 1);
                if (kh == 0) red_s[kw][g][bh * 8 + b][jl] = v;
            }
        __syncthreads();

        // epilogue: threads 0..255, one (b, j) each; sum 8 kw partials
        if (tid < 256) {
            float sr = 0.f, sz = 0.f, sn = 0.f;
            #pragma unroll
            for (int w = 0; w < 8; w++) {
                sr += red_s[w][0][eb][ejl];
                sz += red_s[w][1][eb][ejl];
                sn += red_s[w][2][eb][ejl];
            }
            float r = 1.f / (1.f + expf(-(gr + sr + brc)));
            float z = 1.f / (1.f + expf(-(gz + sz + bzc)));
            float n = tanhf(gn + r * (sn + bnc));
            float hd = hd_s[eb * H + ej];
            float hnew = (1.f - z) * n + z * hd;
            __stcg(&h_out[(size_t)ebg * H + ej], hnew);
            __stcg(&out_s[(size_t)ebg * H + ej], hnew);
        }

        // ---- group barrier (32 CTAs), release/acquire (NO L1 flush) ----
        __syncthreads();
        if (tid == 0) {
            bar_arrive_release(mybar);
            while (bar_poll_acquire(mybar) < target) { }
        }
        __syncthreads();
        target += 32u;
    }
}

// ---------------- launch ----------------
extern "C" void kernel_launch(void* const* d_in, const int* in_sizes, int n_in,
                              void* d_out, int out_size) {
    const float* x     = (const float*)d_in[0];
    const void*  min0  = d_in[1];
    const void*  mh0   = d_in[2];
    const void*  min1  = d_in[3];
    const void*  mh1   = d_in[4];
    const float* w_ih0 = (const float*)d_in[5];
    const float* w_hh0 = (const float*)d_in[6];
    const float* b_ih0 = (const float*)d_in[7];
    const float* b_hh0 = (const float*)d_in[8];
    const float* w_ih1 = (const float*)d_in[9];
    const float* w_hh1 = (const float*)d_in[10];
    const float* b_ih1 = (const float*)d_in[11];
    const float* b_hh1 = (const float*)d_in[12];
    float* out = (float*)d_out;

    float *gi, *out0, *hbuf;
    float4* wt;
    unsigned* bar;
    unsigned char* mbuf;
    cudaGetSymbolAddress((void**)&gi,   g_gi);
    cudaGetSymbolAddress((void**)&out0, g_out0);
    cudaGetSymbolAddress((void**)&hbuf, g_h);
    cudaGetSymbolAddress((void**)&wt,   g_wt);
    cudaGetSymbolAddress((void**)&bar,  g_bar);
    cudaGetSymbolAddress((void**)&mbuf, g_mask);
    const int BH = BATCH * H;                    // 32768
    unsigned char* cmin0 = mbuf;
    unsigned char* cmh0  = mbuf + 32768;
    unsigned char* cmin1 = mbuf + 65536;
    unsigned char* cmh1  = mbuf + 98304;

    const int M = S_LEN * BATCH;                 // 32768
    dim3 gemm_grid(G3H / 128, M / 128);          // (12, 256)

    cudaFuncSetAttribute(gru_layer_kernel,
                         cudaFuncAttributeMaxDynamicSharedMemorySize, GRU_SMEM_BYTES);

    // 1: normalize all masks (fused detect + convert)
    convert_masks_kernel<<<448, 256>>>(min0, mh0, min1, mh1, mbuf);
    // 2: zero h buffers + barrier counters
    reset_kernel<<<(4 * BH + 255) / 256, 256>>>(hbuf);
    // layer 0
    transpose_w_kernel<<<768, 256>>>(w_hh0, wt);
    sgemm_mask_bias_kernel<<<gemm_grid, 256>>>(x, cmin0, w_ih0, b_ih0, gi, DIN);
    gru_layer_kernel<<<NBLK, 512, GRU_SMEM_BYTES>>>(hbuf, hbuf + BH, gi,
                                                    wt, b_hh0, cmh0, out0, bar);
    // layer 1
    transpose_w_kernel<<<768, 256>>>(w_hh1, wt);
    sgemm_mask_bias_kernel<<<gemm_grid, 256>>>(out0, cmin1, w_ih1, b_ih1, gi, H);
    gru_layer_kernel<<<NBLK, 512, GRU_SMEM_BYTES>>>(hbuf + 2 * BH, hbuf + 3 * BH, gi,
                                                    wt, b_hh1, cmh1, out, bar + 4);
    // h_last == out1[S-1]
    copy_kernel<<<(BH + 255) / 256, 256>>>(out + (size_t)(S_LEN - 1) * BH,
                                           out + (size_t)S_LEN * BH, BH);
}